// round 16
// baseline (speedup 1.0000x reference)
#include <cuda_runtime.h>
#include <cuda_fp16.h>
#include <cstdint>

#define NN 500000
#define NE 16000000
#define PROBE_N 1000000

#define ZT 49152                    // src-tile nodes (96 KB fp16)
#define NT 11                       // 11*49152 >= NN
#define ZPAD (ZT * NT)
#define M2 (NT * NN)                // (tile,dst) counters = 5,500,000

#define BLK_S 1024
#define PD 19
#define NCW 5                       // packed count words per thread (19 u8 + pad)
#define CS (BLK_S * PD)             // 19456 dsts per chunk
#define NCHUNK 26                   // 26*19456 >= NN
#define NBLOCKS (NT * NCHUNK)       // 286 spmv CTAs
#define NRUNS (NBLOCKS * BLK_S)     // 292864 thread-runs
#define NRB (NRUNS / 1024)          // 286 (exact)
#define E16LEN (NE + 8 * NRUNS)     // padded edge array (runs 8-aligned)

#define SMEM_S (ZT * 2)             // 96 KB tile -> 2 CTAs/SM

// -------- device scratch (no allocations allowed in kernel_launch) ----------
__device__ int      g_hi_nonzero;   // 0 => adj is int64 (hi words all zero)
__device__ int      g_cnt2[M2];     // per-(tile,dst) edge counts
__device__ int      g_cursor2[M2];  // scatter cursors (abs padded positions)
__device__ uint32_t g_cntP[NBLOCKS * NCW * BLK_S];  // packed counts, transposed
__device__ int      g_runlenp[NRUNS];
__device__ int      g_sR[NRUNS];
__device__ int      g_runstart[NRUNS];
__device__ int      g_bsumR[NRB];
__device__ int      g_bexclR[NRB];
__device__ float    g_dis[NN];
__device__ float    g_acc[NN];      // per-layer edge-sum accumulator (fp32)
__device__ uint16_t g_e16[E16LEN];  // padded edges
__device__ __half   g_za[ZPAD];
__device__ __half   g_zb[ZPAD];

// ----------------------------- cp.async helpers ------------------------------
__device__ __forceinline__ void cp_async16(void* sdst, const void* gsrc) {
    uint32_t s = (uint32_t)__cvta_generic_to_shared(sdst);
    asm volatile("cp.async.cg.shared.global [%0], [%1], 16;\n" :: "r"(s), "l"(gsrc));
}
__device__ __forceinline__ void cp_commit() {
    asm volatile("cp.async.commit_group;\n" ::);
}
template <int N>
__device__ __forceinline__ void cp_wait() {
    asm volatile("cp.async.wait_group %0;\n" :: "n"(N));
}

// byte-sum of a u32 (4 x u8 lanes)
__device__ __forceinline__ int bytesum(uint32_t w) {
    return (int)((w & 0xFFu) + ((w >> 8) & 0xFFu) + ((w >> 16) & 0xFFu) + (w >> 24));
}

// ----------------------------- init + probe ----------------------------------
__global__ void init_kernel() {
    int i = blockIdx.x * blockDim.x + threadIdx.x;
    if (i == 0) g_hi_nonzero = 0;
    if (i < M2) g_cnt2[i] = 0;
    if (i < NN) g_acc[i] = 0.0f;
}

__global__ void probe_kernel(const int* __restrict__ adj32) {
    int i = blockIdx.x * blockDim.x + threadIdx.x;
    int v = (i < PROBE_N) ? adj32[2 * i + 1] : 0;
    #pragma unroll
    for (int o = 16; o > 0; o >>= 1) v |= __shfl_down_sync(0xffffffffu, v, o);
    if ((threadIdx.x & 31) == 0 && v) atomicOr(&g_hi_nonzero, 1);
}

// ----------------------------- precompute -----------------------------------
__global__ void count2_kernel(const int* __restrict__ adj) {
    int e = blockIdx.x * blockDim.x + threadIdx.x;
    if (e >= NE) return;
    int s, d;
    if (g_hi_nonzero == 0) {
        s = ((const int2*)adj)[e].x;
        d = ((const int2*)adj)[NE + e].x;
    } else {
        s = adj[e];
        d = adj[NE + e];
    }
    atomicAdd(&g_cnt2[(s / ZT) * NN + d], 1);
}

__global__ void dis_kernel(const float* __restrict__ x0) {
    int v = blockIdx.x * blockDim.x + threadIdx.x;
    if (v >= NN) return;
    int deg = 0;
    #pragma unroll
    for (int t = 0; t < NT; t++) deg += g_cnt2[t * NN + v];
    float di = rsqrtf((float)(deg + 1));  // +1 self-loop
    g_dis[v] = di;
    g_za[v]  = __float2half(di * x0[v]);
}

// One thread per run: run-local prefix -> cursor2, packed counts, padded len.
__global__ void runprep_kernel() {
    int r = blockIdx.x * blockDim.x + threadIdx.x;
    if (r >= NRUNS) return;
    int block = r / BLK_S;
    int tid   = r - block * BLK_S;
    int t = block / NCHUNK;
    int c = block - t * NCHUNK;
    int dbeg = c * CS + tid * PD;
    int base = t * NN;
    int run = 0;
    uint32_t cw[NCW] = {0, 0, 0, 0, 0};
    #pragma unroll 1
    for (int k = 0; k < PD; k++) {
        int d = dbeg + k;
        int cnt = (d < NN) ? g_cnt2[base + d] : 0;
        if (d < NN) g_cursor2[base + d] = run;       // run-local prefix
        cw[k >> 2] |= (uint32_t)cnt << ((k & 3) << 3);
        run += cnt;
    }
    #pragma unroll
    for (int w = 0; w < NCW; w++)
        g_cntP[(block * NCW + w) * BLK_S + tid] = cw[w];
    g_runlenp[r] = (run + 7) & ~7;                   // pad to 8 (16B) alignment
}

// generic per-block inclusive scan (1024)
__global__ void scan_blk_kernel(const int* __restrict__ in, int* __restrict__ out,
                                int* __restrict__ bsum, int m) {
    __shared__ int sm[1024];
    int t = threadIdx.x;
    int gid = blockIdx.x * 1024 + t;
    int v = (gid < m) ? in[gid] : 0;
    sm[t] = v;
    __syncthreads();
    for (int off = 1; off < 1024; off <<= 1) {
        int tmp = (t >= off) ? sm[t - off] : 0;
        __syncthreads();
        sm[t] += tmp;
        __syncthreads();
    }
    if (gid < m) out[gid] = sm[t];
    if (t == 1023) bsum[blockIdx.x] = sm[1023];
}

__global__ void scan_tiny_kernel(const int* __restrict__ in, int* __restrict__ outExcl, int m) {
    if (threadIdx.x == 0 && blockIdx.x == 0) {
        int run = 0;
        for (int j = 0; j < m; j++) { outExcl[j] = run; run += in[j]; }
    }
}

__global__ void runfix_kernel() {
    int r = blockIdx.x * blockDim.x + threadIdx.x;
    if (r < NRUNS)
        g_runstart[r] = g_sR[r] - g_runlenp[r] + g_bexclR[r >> 10];
}

// cursor2[g] += runstart(run containing g) -> absolute padded positions
__global__ void cursorfix_kernel() {
    int g = blockIdx.x * blockDim.x + threadIdx.x;
    if (g >= M2) return;
    int t = g / NN;
    int d = g - t * NN;
    int c = d / CS;
    int l = d - c * CS;
    int r = (t * NCHUNK + c) * BLK_S + l / PD;
    g_cursor2[g] += g_runstart[r];
}

__global__ void scatter16_kernel(const int* __restrict__ adj) {
    int e = blockIdx.x * blockDim.x + threadIdx.x;
    if (e >= NE) return;
    int s, d;
    if (g_hi_nonzero == 0) {
        s = ((const int2*)adj)[e].x;
        d = ((const int2*)adj)[NE + e].x;
    } else {
        s = adj[e];
        d = adj[NE + e];
    }
    int t = s / ZT;
    int pos = atomicAdd(&g_cursor2[t * NN + d], 1);
    g_e16[pos] = (uint16_t)(s - t * ZT);
}

// ------------------------------ spmv kernel ---------------------------------
// CTA = (tile t, chunk c). Stage z-tile (96 KB). Thread owns 19 consecutive
// dsts; counts arrive via 5 coalesced u32 loads -> register shift-queue;
// edges via aligned uint4 loads over the padded run; per-dst fp32 acc flushed
// with one atomicAdd (REDG) per nonempty dst. All per-layer streams coalesced.
__global__ void __launch_bounds__(BLK_S, 2)
spmv_kernel(int cur_sel)
{
    extern __shared__ __half zt[];   // [ZT]
    int block = blockIdx.x;
    int t = block / NCHUNK;
    int c = block - t * NCHUNK;
    int tid = threadIdx.x;

    const __half* __restrict__ zg = cur_sel ? g_zb : g_za;

    // stage tile t (96 KB)
    {
        const char* src = (const char*)(zg + t * ZT);
        char* dst = (char*)zt;
        #pragma unroll
        for (int i = 0; i < 6; i++) {
            int o = (i * BLK_S + tid) * 16;
            cp_async16(dst + o, src + o);
        }
        cp_commit();
    }

    // coalesced: run start + 5 packed count words
    int e0 = __ldg(&g_runstart[block * BLK_S + tid]);   // 8-aligned
    uint32_t w0 = __ldg(&g_cntP[(block * NCW + 0) * BLK_S + tid]);
    uint32_t w1 = __ldg(&g_cntP[(block * NCW + 1) * BLK_S + tid]);
    uint32_t w2 = __ldg(&g_cntP[(block * NCW + 2) * BLK_S + tid]);
    uint32_t w3 = __ldg(&g_cntP[(block * NCW + 3) * BLK_S + tid]);
    uint32_t w4 = __ldg(&g_cntP[(block * NCW + 4) * BLK_S + tid]);

    int len = bytesum(w0) + bytesum(w1) + bytesum(w2) + bytesum(w3) + bytesum(w4);

    cp_wait<0>();
    __syncthreads();

    if (len > 0) {
        int dbeg = c * CS + tid * PD;

        // register count queue: q0 = counts 0-7, q1 = 8-15, q2 = 16-18
        uint64_t q0 = ((uint64_t)w1 << 32) | w0;
        uint64_t q1 = ((uint64_t)w3 << 32) | w2;
        uint64_t q2 = (uint64_t)w4;
        int phase = 0, rem = 8;
        uint64_t cur = q0;

        int   k   = 0;
        int   cnt;
        float a   = 0.0f;

        auto nextcnt = [&]() -> int {
            if (rem == 0) {
                phase++;
                cur = (phase == 1) ? q1 : q2;
                rem = 8;
            }
            int v = (int)(cur & 0xFF);
            cur >>= 8;
            rem--;
            return v;
        };

        cnt = nextcnt();
        auto emit = [&](int lsrc) {
            while (cnt == 0) {
                if (a != 0.0f) atomicAdd(&g_acc[dbeg + k], a);
                a = 0.0f;
                k++;
                cnt = nextcnt();
            }
            a += __half2float(zt[lsrc]);
            cnt--;
        };

        const uint4* ev = (const uint4*)g_e16 + (e0 >> 3);
        int ng = len >> 3;
        for (int gi = 0; gi < ng; gi++) {
            uint4 u = __ldg(&ev[gi]);
            emit(u.x & 0xFFFF); emit(u.x >> 16);
            emit(u.y & 0xFFFF); emit(u.y >> 16);
            emit(u.z & 0xFFFF); emit(u.z >> 16);
            emit(u.w & 0xFFFF); emit(u.w >> 16);
        }
        for (int j = ng << 3; j < len; j++)
            emit(__ldg(&g_e16[e0 + j]));

        if (a != 0.0f) atomicAdd(&g_acc[dbeg + k], a);
    }
}

// ------------------------------ combine kernel -------------------------------
// h = dis*(acc + z_self); y = (0.7h + 0.3 x0)*w; z' = dis*act(y); acc := 0.
__global__ void combine_kernel(const float* __restrict__ x0,
                               const float* __restrict__ w,
                               float* __restrict__ out,
                               int layer, int act, int cur_sel)
{
    int v0 = (blockIdx.x * blockDim.x + threadIdx.x) * 4;
    if (v0 >= NN) return;   // NN % 4 == 0

    const __half* __restrict__ zg = cur_sel ? g_zb : g_za;

    float4 av = *(float4*)&g_acc[v0];
    *(float4*)&g_acc[v0] = make_float4(0.f, 0.f, 0.f, 0.f);  // zero for next layer

    float4 dv = *(const float4*)&g_dis[v0];
    float4 xv = *(const float4*)&x0[v0];
    __half2 zs01 = *(const __half2*)&zg[v0];
    __half2 zs23 = *(const __half2*)&zg[v0 + 2];
    float wl = __ldg(&w[layer]);

    float h0 = dv.x * (av.x + __half2float(zs01.x));
    float h1 = dv.y * (av.y + __half2float(zs01.y));
    float h2 = dv.z * (av.z + __half2float(zs23.x));
    float h3 = dv.w * (av.w + __half2float(zs23.y));
    float y0 = (0.7f * h0 + 0.3f * xv.x) * wl;
    float y1 = (0.7f * h1 + 0.3f * xv.y) * wl;
    float y2 = (0.7f * h2 + 0.3f * xv.z) * wl;
    float y3 = (0.7f * h3 + 0.3f * xv.w) * wl;

    if (act == 4) {
        // astype(int) truncates toward zero; value < 2^24 -> exact in fp32.
        float4 o;
        o.x = truncf(500000.0f / (1.0f + expf(-y0)));
        o.y = truncf(500000.0f / (1.0f + expf(-y1)));
        o.z = truncf(500000.0f / (1.0f + expf(-y2)));
        o.w = truncf(500000.0f / (1.0f + expf(-y3)));
        *(float4*)&out[v0] = o;
        return;
    }
    float r0, r1, r2, r3;
    if      (act == 0) { r0 = y0; r1 = y1; r2 = y2; r3 = y3; }
    else if (act == 1) {
        r0 = (y0 > 0.f) ? y0 : 0.01f * y0;  r1 = (y1 > 0.f) ? y1 : 0.01f * y1;
        r2 = (y2 > 0.f) ? y2 : 0.01f * y2;  r3 = (y3 > 0.f) ? y3 : 0.01f * y3;
    } else if (act == 2) {
        r0 = 1.0f / (1.0f + expf(-y0));  r1 = 1.0f / (1.0f + expf(-y1));
        r2 = 1.0f / (1.0f + expf(-y2));  r3 = 1.0f / (1.0f + expf(-y3));
    } else {
        r0 = fmaxf(y0, 0.f); r1 = fmaxf(y1, 0.f);
        r2 = fmaxf(y2, 0.f); r3 = fmaxf(y3, 0.f);
    }

    __half* zn = cur_sel ? g_za : g_zb;
    *(__half2*)&zn[v0]     = __floats2half2_rn(dv.x * r0, dv.y * r1);
    *(__half2*)&zn[v0 + 2] = __floats2half2_rn(dv.z * r2, dv.w * r3);
}

// ------------------------------- host entry ---------------------------------
extern "C" void kernel_launch(void* const* d_in, const int* in_sizes, int n_in,
                              void* d_out, int out_size)
{
    const float* input = nullptr;
    const float* w     = nullptr;
    const int*   adj   = nullptr;
    for (int i = 0; i < n_in; i++) {
        if      (in_sizes[i] == 49) w     = (const float*)d_in[i];
        else if (in_sizes[i] == NN) input = (const float*)d_in[i];
        else                        adj   = (const int*)d_in[i];
    }
    float* out = (float*)d_out;

    cudaFuncSetAttribute(spmv_kernel,
                         cudaFuncAttributeMaxDynamicSharedMemorySize, SMEM_S);

    int nb_m2    = (M2 + 255) / 256;
    int nb_nodes = (NN + 255) / 256;
    int nb_edges = (NE + 255) / 256;
    int nb_probe = (PROBE_N + 255) / 256;
    int nb_runs  = (NRUNS + 255) / 256;

    init_kernel     <<<nb_m2, 256>>>();
    probe_kernel    <<<nb_probe, 256>>>(adj);
    count2_kernel   <<<nb_edges, 256>>>(adj);
    dis_kernel      <<<nb_nodes, 256>>>(input);
    runprep_kernel  <<<nb_runs, 256>>>();
    scan_blk_kernel <<<NRB, 1024>>>(g_runlenp, g_sR, g_bsumR, NRUNS);
    scan_tiny_kernel<<<1, 32>>>(g_bsumR, g_bexclR, NRB);
    runfix_kernel   <<<nb_runs, 256>>>();
    cursorfix_kernel<<<nb_m2, 256>>>();
    scatter16_kernel<<<nb_edges, 256>>>(adj);

    int nb_comb = (NN / 4 + 255) / 256;
    int cur = 0;   // z0 lives in g_za
    for (int i = 0; i < 49; i++) {
        int act;
        if      (i == 48) act = 4;
        else if (i == 0)  act = 0;
        else if (i == 1 || i == 11 || i == 21 || i == 31 || i == 41) act = 1;
        else if (i == 4 || i == 14 || i == 24 || i == 34 || i == 44) act = 2;
        else act = 3;
        spmv_kernel   <<<NBLOCKS, BLK_S, SMEM_S>>>(cur);
        combine_kernel<<<nb_comb, 256>>>(input, w, out, i, act, cur);
        cur ^= 1;
    }
}